// round 9
// baseline (speedup 1.0000x reference)
#include <cuda_runtime.h>
#include <math.h>

#define TPBA 512          // scan block
#define NWA  (TPBA / 32)  // 16 warps
#define TPBB 128          // finalize block
#define KC   10           // n_point_candidate
#define NKP  9            // 8 keypoints + 1 center
#define CAPB 512          // per-scan-block survivor capacity (expected ~11)
#define REGC 3            // float4 per thread in registers (half <= TPBA*REGC*4)
#define MAXB 64

__device__ float g_cv[MAXB * 2 * CAPB];
__device__ int   g_ci[MAXB * 2 * CAPB];
__device__ int   g_cnt[MAXB * 2];

// order-preserving float -> uint key
__device__ __forceinline__ unsigned fkey(float x) {
    unsigned u = __float_as_uint(x);
    return (u & 0x80000000u) ? ~u : (u | 0x80000000u);
}
__device__ __forceinline__ float funkey(unsigned k) {
    return __uint_as_float((k & 0x80000000u) ? (k & 0x7FFFFFFFu) : ~k);
}

// ---------------------------------------------------------------------------
// Kernel A: half-batch scan -> survivors >= (10th-largest warp max)
// grid = (b, 2), block = TPBA
// ---------------------------------------------------------------------------
__global__ __launch_bounds__(TPBA)
void scan_kernel(const float* __restrict__ seg, int n)
{
    const int b   = blockIdx.x;
    const int s   = blockIdx.y;
    const int tid = threadIdx.x;

    __shared__ unsigned wmaxk[NWA];
    __shared__ float sT;
    __shared__ int   scnt;
    if (tid == 0) scnt = 0;

    const float*  segb = seg + (long long)b * n;
    const int     nf4  = n >> 2;
    const float4* seg4 = (const float4*)segb;
    const int     half4  = (nf4 + 1) >> 1;
    const int     begin4 = s * half4;
    const int     end4   = min(nf4, begin4 + half4);
    const int     regEnd = begin4 + TPBA * REGC;

    // single load pass into registers (REGC independent LDG.128)
    float4 buf[REGC];
#pragma unroll
    for (int j = 0; j < REGC; j++) {
        int i4 = begin4 + tid + j * TPBA;
        buf[j] = (i4 < end4) ? seg4[i4]
                             : make_float4(-INFINITY, -INFINITY, -INFINITY, -INFINITY);
    }

    // per-vector maxes (reused by the filter) + thread max
    float v4m[REGC];
#pragma unroll
    for (int j = 0; j < REGC; j++)
        v4m[j] = fmaxf(fmaxf(buf[j].x, buf[j].y), fmaxf(buf[j].z, buf[j].w));
    float m = v4m[0];
#pragma unroll
    for (int j = 1; j < REGC; j++) m = fmaxf(m, v4m[j]);

    // fallback beyond register coverage (not taken at n = 12288)
    for (int i4 = regEnd + tid; i4 < end4; i4 += TPBA) {
        float4 v = seg4[i4];
        m = fmaxf(m, fmaxf(fmaxf(v.x, v.y), fmaxf(v.z, v.w)));
    }
    // scalar tail (n % 4), handled by s == 1
    if (s == 1)
        for (int i = (nf4 << 2) + tid; i < n; i += TPBA)
            m = fmaxf(m, segb[i]);

    // warp max via REDUX on order-preserving key
    unsigned mk = __reduce_max_sync(0xFFFFFFFFu, fkey(m));
    if ((tid & 31) == 0) wmaxk[tid >> 5] = mk;
    __syncthreads();

    // block threshold T = 10th-largest warp max (rank KC-1):
    // 10 disjoint warps each hold >=1 element >= T  =>  block top-10 all >= T.
    if (tid < NWA) {
        unsigned v = wmaxk[tid];
        int rank = 0;
#pragma unroll
        for (int j = 0; j < NWA; j++) {
            unsigned vj = wmaxk[j];
            rank += (vj > v) || (vj == v && j < tid);
        }
        if (rank == KC - 1) sT = funkey(v);
    }
    __syncthreads();
    const float T = sT;

    float* cvb = g_cv + (b * 2 + s) * CAPB;
    int*   cib = g_ci + (b * 2 + s) * CAPB;

    // filter from registers, warp-uniform skip then per-vector skip
    if (funkey(mk) >= T) {
#pragma unroll
        for (int j = 0; j < REGC; j++) {
            if (v4m[j] >= T) {
                int i4 = begin4 + tid + j * TPBA;
                float xs[4] = {buf[j].x, buf[j].y, buf[j].z, buf[j].w};
#pragma unroll
                for (int c = 0; c < 4; c++) {
                    if (xs[c] >= T) {
                        int sl = atomicAdd(&scnt, 1);
                        if (sl < CAPB) { cvb[sl] = xs[c]; cib[sl] = (i4 << 2) + c; }
                    }
                }
            }
        }
    }
    // fallback + tail rescan memory (not taken / tiny)
    for (int i4 = regEnd + tid; i4 < end4; i4 += TPBA) {
        float4 v = seg4[i4];
        float xs[4] = {v.x, v.y, v.z, v.w};
#pragma unroll
        for (int c = 0; c < 4; c++)
            if (xs[c] >= T) {
                int sl = atomicAdd(&scnt, 1);
                if (sl < CAPB) { cvb[sl] = xs[c]; cib[sl] = (i4 << 2) + c; }
            }
    }
    if (s == 1)
        for (int i = (nf4 << 2) + tid; i < n; i += TPBA) {
            float x = segb[i];
            if (x >= T) {
                int sl = atomicAdd(&scnt, 1);
                if (sl < CAPB) { cvb[sl] = x; cib[sl] = i; }
            }
        }
    __syncthreads();
    if (tid == 0) g_cnt[b * 2 + s] = min(scnt, CAPB);
}

// ---------------------------------------------------------------------------
// Kernel B: merge survivors -> exact top-10 -> candidates -> cluster -> Kabsch
// grid = b, block = TPBB
// ---------------------------------------------------------------------------
__global__ __launch_bounds__(TPBB)
void finalize_kernel(const float* __restrict__ pcld,
                     const float* __restrict__ kpts,
                     const float* __restrict__ cpt,
                     const float* __restrict__ mesh,
                     float* __restrict__ outR,
                     float* __restrict__ outT,
                     float* __restrict__ outV,
                     int n)
{
    const int b   = blockIdx.x;
    const int tid = threadIdx.x;

    __shared__ float smesh[NKP * 3];
    __shared__ float cv[2 * CAPB];
    __shared__ int   ci[2 * CAPB];
    __shared__ int   stot;
    __shared__ int   topi[KC];
    __shared__ float cand[NKP][KC][3];
    __shared__ float voted[NKP][3];

    if (tid < NKP * 3) smesh[tid] = mesh[(long long)b * NKP * 3 + tid];

    // gather both survivor lists into shared
    int c0 = g_cnt[b * 2 + 0];
    int c1 = g_cnt[b * 2 + 1];
    if (tid == 0) stot = c0 + c1;
    for (int i = tid; i < c0; i += TPBB) {
        cv[i] = g_cv[(b * 2 + 0) * CAPB + i];
        ci[i] = g_ci[(b * 2 + 0) * CAPB + i];
    }
    for (int i = tid; i < c1; i += TPBB) {
        cv[c0 + i] = g_cv[(b * 2 + 1) * CAPB + i];
        ci[c0 + i] = g_ci[(b * 2 + 1) * CAPB + i];
    }
    __syncthreads();

    // exact top-10 by rank-count over ~22 survivors
    const int tot = stot;
    for (int i = tid; i < tot; i += TPBB) {
        float v = cv[i]; int id = ci[i];
        int rank = 0;
        for (int j = 0; j < tot; j++) {
            float vj = cv[j];
            rank += (vj > v) || (vj == v && ci[j] < id);
        }
        if (rank < KC) topi[rank] = id;
    }
    __syncthreads();

    // build candidates (90 threads)
    if (tid < NKP * KC) {
        int i  = tid / KC;
        int j  = tid % KC;
        int id = topi[j];
        const float* p = pcld + ((long long)b * n + id) * 3;
        const float* o = (i < 8)
            ? (kpts + (((long long)b * n + id) * 8 + i) * 3)
            : (cpt  + ((long long)b * n + id) * 3);
        cand[i][j][0] = p[0] + o[0];
        cand[i][j][1] = p[1] + o[1];
        cand[i][j][2] = p[2] + o[2];
    }
    __syncthreads();

    // clustering with std filter (9 threads)
    if (tid < NKP) {
        float m0 = 0.f, m1 = 0.f, m2 = 0.f;
#pragma unroll
        for (int j = 0; j < KC; j++) { m0 += cand[tid][j][0]; m1 += cand[tid][j][1]; m2 += cand[tid][j][2]; }
        m0 *= 0.1f; m1 *= 0.1f; m2 *= 0.1f;
        float v0 = 0.f, v1 = 0.f, v2 = 0.f;
#pragma unroll
        for (int j = 0; j < KC; j++) {
            float d0 = cand[tid][j][0] - m0, d1 = cand[tid][j][1] - m1, d2 = cand[tid][j][2] - m2;
            v0 += d0 * d0; v1 += d1 * d1; v2 += d2 * d2;
        }
        float s0 = sqrtf(v0 * 0.1f), s1 = sqrtf(v1 * 0.1f), s2 = sqrtf(v2 * 0.1f);
        float a0 = 0.f, a1 = 0.f, a2 = 0.f, cc = 0.f;
#pragma unroll
        for (int j = 0; j < KC; j++) {
            float c0v = cand[tid][j][0], c1v = cand[tid][j][1], c2v = cand[tid][j][2];
            bool in = (fabsf(c0v - m0) <= s0) && (fabsf(c1v - m1) <= s1) && (fabsf(c2v - m2) <= s2);
            if (in) { cc += 1.f; a0 += c0v; a1 += c1v; a2 += c2v; }
        }
        float inv = __fdividef(1.0f, cc + 1e-6f);
        float w0 = a0 * inv, w1 = a1 * inv, w2 = a2 * inv;
        voted[tid][0] = w0; voted[tid][1] = w1; voted[tid][2] = w2;
        long long vo = ((long long)b * NKP + tid) * 3;
        outV[vo + 0] = w0; outV[vo + 1] = w1; outV[vo + 2] = w2;
    }
    __syncthreads();

    // Kabsch + closed-form 3x3 eigen (thread 0)
    if (tid == 0) {
        float cA[3] = {0, 0, 0}, cB[3] = {0, 0, 0};
#pragma unroll
        for (int i = 0; i < NKP; i++) {
            cA[0] += smesh[i * 3 + 0]; cA[1] += smesh[i * 3 + 1]; cA[2] += smesh[i * 3 + 2];
            cB[0] += voted[i][0];      cB[1] += voted[i][1];      cB[2] += voted[i][2];
        }
        const float inv9 = 1.0f / 9.0f;
        cA[0] *= inv9; cA[1] *= inv9; cA[2] *= inv9;
        cB[0] *= inv9; cB[1] *= inv9; cB[2] *= inv9;

        float H[3][3] = {{0,0,0},{0,0,0},{0,0,0}};
#pragma unroll
        for (int i = 0; i < NKP; i++) {
            float am[3] = {smesh[i*3+0] - cA[0], smesh[i*3+1] - cA[1], smesh[i*3+2] - cA[2]};
            float bm[3] = {voted[i][0] - cB[0], voted[i][1] - cB[1], voted[i][2] - cB[2]};
#pragma unroll
            for (int r = 0; r < 3; r++)
#pragma unroll
                for (int c = 0; c < 3; c++)
                    H[r][c] += am[r] * bm[c];
        }

        float K[3][3];
#pragma unroll
        for (int r = 0; r < 3; r++)
#pragma unroll
            for (int c = 0; c < 3; c++)
                K[r][c] = H[0][r]*H[0][c] + H[1][r]*H[1][c] + H[2][r]*H[2][c];

        float v1[3] = {1.f, 0.f, 0.f}, v2[3] = {0.f, 1.f, 0.f};
        {
            float q  = (K[0][0] + K[1][1] + K[2][2]) * (1.0f / 3.0f);
            float p1 = K[0][1]*K[0][1] + K[0][2]*K[0][2] + K[1][2]*K[1][2];
            float b0 = K[0][0] - q, b1 = K[1][1] - q, b2 = K[2][2] - q;
            float p2 = b0*b0 + b1*b1 + b2*b2 + 2.0f * p1;
            if (p2 > 1e-30f) {
                float pp   = p2 * (1.0f / 6.0f);
                float invp = __frsqrt_rn(pp);
                float p    = pp * invp;
                float detB = b0 * (b1*b2 - K[1][2]*K[1][2])
                           - K[0][1] * (K[0][1]*b2 - K[1][2]*K[0][2])
                           + K[0][2] * (K[0][1]*K[1][2] - b1*K[0][2]);
                float r = detB * 0.5f * invp * invp * invp;
                r = fminf(1.0f, fmaxf(-1.0f, r));
                float phi = acosf(r) * (1.0f / 3.0f);
                float e1 = q + 2.0f * p * __cosf(phi);
                float e3 = q + 2.0f * p * __cosf(phi + 2.0943951023931953f);
                float e2 = 3.0f * q - e1 - e3;

                // eigenvectors: largest cross product of rows of K - lam*I
                auto eigvec = [&](float lam, float v[3]) {
                    float a00 = K[0][0] - lam, a11 = K[1][1] - lam, a22 = K[2][2] - lam;
                    float a01 = K[0][1], a02 = K[0][2], a12 = K[1][2];
                    float c0x = a01*a12 - a02*a11, c0y = a02*a01 - a00*a12, c0z = a00*a11 - a01*a01;
                    float c1x = a01*a22 - a02*a12, c1y = a02*a02 - a00*a22, c1z = a00*a12 - a01*a02;
                    float c2x = a11*a22 - a12*a12, c2y = a12*a02 - a01*a22, c2z = a01*a12 - a11*a02;
                    float n0 = c0x*c0x + c0y*c0y + c0z*c0z;
                    float n1 = c1x*c1x + c1y*c1y + c1z*c1z;
                    float n2 = c2x*c2x + c2y*c2y + c2z*c2z;
                    float bx = c0x, by = c0y, bz = c0z, bn = n0;
                    if (n1 > bn) { bx = c1x; by = c1y; bz = c1z; bn = n1; }
                    if (n2 > bn) { bx = c2x; by = c2y; bz = c2z; bn = n2; }
                    float iv = (bn > 1e-30f) ? __frsqrt_rn(bn) : 0.0f;
                    v[0] = bx * iv; v[1] = by * iv; v[2] = bz * iv;
                };
                eigvec(e1, v1);
                eigvec(e2, v2);
                float d = v2[0]*v1[0] + v2[1]*v1[1] + v2[2]*v1[2];
                v2[0] -= d * v1[0]; v2[1] -= d * v1[1]; v2[2] -= d * v1[2];
                float nn = v2[0]*v2[0] + v2[1]*v2[1] + v2[2]*v2[2];
                float ii = (nn > 1e-30f) ? __frsqrt_rn(nn) : 0.0f;
                v2[0] *= ii; v2[1] *= ii; v2[2] *= ii;
            }
        }
        float v3[3] = { v1[1]*v2[2] - v1[2]*v2[1],
                        v1[2]*v2[0] - v1[0]*v2[2],
                        v1[0]*v2[1] - v1[1]*v2[0] };

        float u1[3], u2[3], u3[3];
#pragma unroll
        for (int r = 0; r < 3; r++) u1[r] = H[r][0]*v1[0] + H[r][1]*v1[1] + H[r][2]*v1[2];
        float d1 = u1[0]*u1[0] + u1[1]*u1[1] + u1[2]*u1[2];
        float in1 = (d1 > 1e-30f) ? __frsqrt_rn(d1) : 0.0f;
        u1[0] *= in1; u1[1] *= in1; u1[2] *= in1;

#pragma unroll
        for (int r = 0; r < 3; r++) u2[r] = H[r][0]*v2[0] + H[r][1]*v2[1] + H[r][2]*v2[2];
        float d12 = u2[0]*u1[0] + u2[1]*u1[1] + u2[2]*u1[2];
        u2[0] -= d12 * u1[0]; u2[1] -= d12 * u1[1]; u2[2] -= d12 * u1[2];
        float d2 = u2[0]*u2[0] + u2[1]*u2[1] + u2[2]*u2[2];
        float in2 = (d2 > 1e-30f) ? __frsqrt_rn(d2) : 0.0f;
        u2[0] *= in2; u2[1] *= in2; u2[2] *= in2;

        u3[0] = u1[1]*u2[2] - u1[2]*u2[1];
        u3[1] = u1[2]*u2[0] - u1[0]*u2[2];
        u3[2] = u1[0]*u2[1] - u1[1]*u2[0];

        float R[3][3];
#pragma unroll
        for (int r = 0; r < 3; r++)
#pragma unroll
            for (int c = 0; c < 3; c++)
                R[r][c] = v1[r]*u1[c] + v2[r]*u2[c] + v3[r]*u3[c];

        float det = R[0][0]*(R[1][1]*R[2][2] - R[1][2]*R[2][1])
                  - R[0][1]*(R[1][0]*R[2][2] - R[1][2]*R[2][0])
                  + R[0][2]*(R[1][0]*R[2][1] - R[1][1]*R[2][0]);
        if (det < 0.0f) {
#pragma unroll
            for (int r = 0; r < 3; r++)
#pragma unroll
                for (int c = 0; c < 3; c++)
                    R[r][c] -= 2.0f * v3[r] * u3[c];
        }

        long long ro = (long long)b * 9;
#pragma unroll
        for (int r = 0; r < 3; r++)
#pragma unroll
            for (int c = 0; c < 3; c++)
                outR[ro + r*3 + c] = R[r][c];

        long long to = (long long)b * 3;
#pragma unroll
        for (int c = 0; c < 3; c++) {
            float tc = cB[c] - (R[c][0]*cA[0] + R[c][1]*cA[1] + R[c][2]*cA[2]);
            outT[to + c] = tc;
        }
    }
}

extern "C" void kernel_launch(void* const* d_in, const int* in_sizes, int n_in,
                              void* d_out, int out_size)
{
    const float* pcld = (const float*)d_in[0];  // [b,n,3]
    const float* kpts = (const float*)d_in[1];  // [b,n,8,3]
    const float* cpt  = (const float*)d_in[2];  // [b,n,1,3]
    const float* seg  = (const float*)d_in[3];  // [b,n,1]
    const float* mesh = (const float*)d_in[4];  // [b,9,3]

    int b = in_sizes[4] / 27;       // mesh is b*9*3
    int n = in_sizes[3] / b;        // seg is b*n

    float* out  = (float*)d_out;
    float* outR = out;                      // b*9
    float* outT = out + (long long)b * 9;   // b*3
    float* outV = out + (long long)b * 12;  // b*27

    dim3 gridA(b, 2);
    scan_kernel<<<gridA, TPBA>>>(seg, n);
    finalize_kernel<<<b, TPBB>>>(pcld, kpts, cpt, mesh, outR, outT, outV, n);
}